// round 16
// baseline (speedup 1.0000x reference)
#include <cuda_runtime.h>
#include <cuda_bf16.h>
#include <math.h>

#define Bv   64
#define Nv   256
#define Din  16
#define Hv   128
#define Lv   6
#define DFFv 2048
#define HEADSv 8
#define DHv  16
#define TOURLEN 16
#define LSCALE 0.08838834764831845f   /* H^-0.5 */
#define SPLITK 4

// -------------------- device scratch (no allocations allowed) --------------------
__device__ float g_h[Bv*Nv*Hv];
__device__ float g_qkv[Bv*Nv*3*Hv];
__device__ float g_att[Bv*Nv*Hv];
__device__ float g_ff[Bv*Nv*DFFv];
__device__ float g_part[SPLITK*Bv*Nv*Hv];
__device__ float g_k[Bv*Nv*Hv];
__device__ float g_M[Bv*Nv*Hv];
__device__ float g_baseQ[Bv*Nv*Hv];
__device__ float g_graph[Bv*Hv];
__device__ float g_gq[Bv*Hv];
__device__ float g_W1q[Hv*Hv];
__device__ float g_W2q[Hv*Hv];
__device__ float g_W3q[Hv*Hv];
__device__ float g_bq2[Hv];
__device__ float g_baseLT[Bv*Nv*Nv];   // TRANSPOSED: [b][n][s]
__device__ float g_cross[Bv*Nv*Nv];    // [b][c][n]

// -------------------- packed fp32x2 helpers (Blackwell) --------------------
__device__ __forceinline__ unsigned long long bcast2(float x) {
    unsigned long long r;
    asm("mov.b64 %0, {%1, %1};" : "=l"(r) : "f"(x));
    return r;
}
__device__ __forceinline__ void fma2(unsigned long long& d,
                                     unsigned long long a, unsigned long long b) {
    asm("fma.rn.f32x2 %0, %1, %2, %0;" : "+l"(d) : "l"(a), "l"(b));
}
__device__ __forceinline__ float2 unpk2(unsigned long long v) {
    float lo, hi;
    asm("mov.b64 {%0, %1}, %2;" : "=f"(lo), "=f"(hi) : "l"(v));
    return make_float2(lo, hi);
}

// ============================================================================
// SGEMM, BN=128, BK=16, 256 threads, double-buffered smem + PIPELINED fragments.
// Fragment for step kk+1 is prefetched into registers while kk computes, hiding
// the 29-cycle LDS latency in-warp. FMA order per accumulator unchanged.
// blockIdx.z = K-slice index: kbeg = z*K/gridDim.z, C += z*strCz.
// EPI: 0 = optional bias, 1 = bias+relu, 2 = bias+residual+LayerNorm (N==128)
// ============================================================================
template<int BM, int EPI>
__global__ __launch_bounds__(256)
void sgemm_k(const float* __restrict__ A, const float* __restrict__ B,
             const float* __restrict__ bias, const float* __restrict__ res,
             const float* __restrict__ lng, const float* __restrict__ lnb,
             float* __restrict__ C, int M, int N, int K, size_t strCz)
{
    constexpr int TM = BM / 16;
    constexpr int TP = TM / 2;
    constexpr int NA = (BM * 16) / 1024;
    __shared__ __align__(16) float As[2][16][BM];
    __shared__ __align__(16) float Bs[2][16][128];

    const int tid = threadIdx.x;
    const int tx = tid & 15, ty = tid >> 4;
    const int bm = blockIdx.y * BM;
    const int bn = blockIdx.x * 128;
    const int kslice = K / gridDim.z;
    const int kbeg = blockIdx.z * kslice;
    const int kend = kbeg + kslice;
    C += (size_t)blockIdx.z * strCz;

    const float* Ab = A + (size_t)bm * K;
    const float* Bb = B + bn;

    float4 ra[NA], rb[2];

    #pragma unroll
    for (int i = 0; i < NA; i++) {
        int lin = tid + i * 256;
        int r = lin >> 2, c4 = (lin & 3) << 2;
        ra[i] = *(const float4*)(Ab + (size_t)r * K + kbeg + c4);
    }
    #pragma unroll
    for (int i = 0; i < 2; i++) {
        int lin = tid + i * 256;
        int r = lin >> 5, c4 = (lin & 31) << 2;
        rb[i] = *(const float4*)(Bb + (size_t)(kbeg + r) * N + c4);
    }
    #pragma unroll
    for (int i = 0; i < NA; i++) {
        int lin = tid + i * 256;
        int r = lin >> 2, c4 = (lin & 3) << 2;
        As[0][c4 + 0][r] = ra[i].x; As[0][c4 + 1][r] = ra[i].y;
        As[0][c4 + 2][r] = ra[i].z; As[0][c4 + 3][r] = ra[i].w;
    }
    #pragma unroll
    for (int i = 0; i < 2; i++) {
        int lin = tid + i * 256;
        int r = lin >> 5, c4 = (lin & 31) << 2;
        *(float4*)&Bs[0][r][c4] = rb[i];
    }
    __syncthreads();

    unsigned long long acc[TP][8];
    #pragma unroll
    for (int i = 0; i < TP; i++)
        #pragma unroll
        for (int j = 0; j < 8; j++) acc[i][j] = 0ull;

    int buf = 0;
    for (int k0 = kbeg; k0 < kend; k0 += 16) {
        const bool has_next = (k0 + 16) < kend;
        if (has_next) {
            #pragma unroll
            for (int i = 0; i < NA; i++) {
                int lin = tid + i * 256;
                int r = lin >> 2, c4 = (lin & 3) << 2;
                ra[i] = *(const float4*)(Ab + (size_t)r * K + k0 + 16 + c4);
            }
            #pragma unroll
            for (int i = 0; i < 2; i++) {
                int lin = tid + i * 256;
                int r = lin >> 5, c4 = (lin & 31) << 2;
                rb[i] = *(const float4*)(Bb + (size_t)(k0 + 16 + r) * N + c4);
            }
        }
        // ---- pipelined fragment loop: prefetch kk+1 while computing kk
        unsigned long long faC[TP], faN[TP];
        float4 fb0C, fb1C, fb0N, fb1N;
        #pragma unroll
        for (int i = 0; i < TP; i++)
            faC[i] = *(const unsigned long long*)&As[buf][0][ty * TM + i * 2];
        fb0C = *(const float4*)&Bs[buf][0][tx * 8];
        fb1C = *(const float4*)&Bs[buf][0][tx * 8 + 4];
        #pragma unroll
        for (int kk = 0; kk < 16; kk++) {
            if (kk < 15) {
                #pragma unroll
                for (int i = 0; i < TP; i++)
                    faN[i] = *(const unsigned long long*)&As[buf][kk + 1][ty * TM + i * 2];
                fb0N = *(const float4*)&Bs[buf][kk + 1][tx * 8];
                fb1N = *(const float4*)&Bs[buf][kk + 1][tx * 8 + 4];
            }
            unsigned long long bb[8];
            bb[0] = bcast2(fb0C.x); bb[1] = bcast2(fb0C.y);
            bb[2] = bcast2(fb0C.z); bb[3] = bcast2(fb0C.w);
            bb[4] = bcast2(fb1C.x); bb[5] = bcast2(fb1C.y);
            bb[6] = bcast2(fb1C.z); bb[7] = bcast2(fb1C.w);
            #pragma unroll
            for (int i = 0; i < TP; i++)
                #pragma unroll
                for (int j = 0; j < 8; j++) fma2(acc[i][j], faC[i], bb[j]);
            if (kk < 15) {
                #pragma unroll
                for (int i = 0; i < TP; i++) faC[i] = faN[i];
                fb0C = fb0N; fb1C = fb1N;
            }
        }
        if (has_next) {
            int nb = buf ^ 1;
            #pragma unroll
            for (int i = 0; i < NA; i++) {
                int lin = tid + i * 256;
                int r = lin >> 2, c4 = (lin & 3) << 2;
                As[nb][c4 + 0][r] = ra[i].x; As[nb][c4 + 1][r] = ra[i].y;
                As[nb][c4 + 2][r] = ra[i].z; As[nb][c4 + 3][r] = ra[i].w;
            }
            #pragma unroll
            for (int i = 0; i < 2; i++) {
                int lin = tid + i * 256;
                int r = lin >> 5, c4 = (lin & 31) << 2;
                *(float4*)&Bs[nb][r][c4] = rb[i];
            }
            __syncthreads();
            buf = nb;
        }
    }

    // ---- epilogue
    float bv[8] = {0.f,0.f,0.f,0.f,0.f,0.f,0.f,0.f};
    if (bias) {
        *(float4*)&bv[0] = *(const float4*)(bias + bn + tx * 8);
        *(float4*)&bv[4] = *(const float4*)(bias + bn + tx * 8 + 4);
    }

    if (EPI == 2) {
        float gv[8], be[8];
        *(float4*)&gv[0] = *(const float4*)(lng + tx * 8);
        *(float4*)&gv[4] = *(const float4*)(lng + tx * 8 + 4);
        *(float4*)&be[0] = *(const float4*)(lnb + tx * 8);
        *(float4*)&be[4] = *(const float4*)(lnb + tx * 8 + 4);
        #pragma unroll
        for (int ip = 0; ip < TP; ip++) {
            #pragma unroll
            for (int e = 0; e < 2; e++) {
                int row = bm + ty * TM + ip * 2 + e;
                const float* rp = res + (size_t)row * 128 + tx * 8;
                float4 r0 = *(const float4*)rp;
                float4 r1 = *(const float4*)(rp + 4);
                float v[8];
                #pragma unroll
                for (int j = 0; j < 8; j++) {
                    float2 p = unpk2(acc[ip][j]);
                    v[j] = (e == 0 ? p.x : p.y) + bv[j];
                }
                v[0] += r0.x; v[1] += r0.y; v[2] += r0.z; v[3] += r0.w;
                v[4] += r1.x; v[5] += r1.y; v[6] += r1.z; v[7] += r1.w;
                float s = 0.f, s2 = 0.f;
                #pragma unroll
                for (int j = 0; j < 8; j++) { s += v[j]; s2 += v[j] * v[j]; }
                #pragma unroll
                for (int m = 8; m >= 1; m >>= 1) {
                    s  += __shfl_xor_sync(0xffffffffu, s,  m);
                    s2 += __shfl_xor_sync(0xffffffffu, s2, m);
                }
                float mu  = s * (1.f / 128.f);
                float var = s2 * (1.f / 128.f) - mu * mu;
                float rs  = rsqrtf(var + 1e-5f);
                float o[8];
                #pragma unroll
                for (int j = 0; j < 8; j++) o[j] = (v[j] - mu) * rs * gv[j] + be[j];
                float* cp = C + (size_t)row * 128 + tx * 8;
                *(float4*)cp       = *(float4*)&o[0];
                *(float4*)(cp + 4) = *(float4*)&o[4];
            }
        }
    } else {
        #pragma unroll
        for (int ip = 0; ip < TP; ip++) {
            #pragma unroll
            for (int e = 0; e < 2; e++) {
                int row = bm + ty * TM + ip * 2 + e;
                float o[8];
                #pragma unroll
                for (int j = 0; j < 8; j++) {
                    float2 p = unpk2(acc[ip][j]);
                    float v = (e == 0 ? p.x : p.y) + bv[j];
                    if (EPI == 1) v = fmaxf(v, 0.f);
                    o[j] = v;
                }
                float* cp = C + (size_t)row * N + bn + tx * 8;
                *(float4*)cp       = *(float4*)&o[0];
                *(float4*)(cp + 4) = *(float4*)&o[4];
            }
        }
    }
}

// ---- split-K reduce + bias + residual + LayerNorm (R13-proven)
__global__ __launch_bounds__(128)
void reduce_ln(const float* __restrict__ part, const float* __restrict__ bias,
               const float* __restrict__ res, const float* __restrict__ g,
               const float* __restrict__ be, float* __restrict__ out)
{
    const int row = blockIdx.x, t = threadIdx.x;
    const size_t stride = (size_t)Bv * Nv * Hv;
    float v = part[(size_t)row * Hv + t];
    #pragma unroll
    for (int z = 1; z < SPLITK; z++) v += part[z * stride + (size_t)row * Hv + t];
    v += bias[t] + res[(size_t)row * Hv + t];

    __shared__ float ws[4], ws2[4];
    int lane = t & 31, wid = t >> 5;
    float s = v, s2 = v * v;
    #pragma unroll
    for (int o = 16; o > 0; o >>= 1) {
        s  += __shfl_xor_sync(0xffffffffu, s,  o);
        s2 += __shfl_xor_sync(0xffffffffu, s2, o);
    }
    if (lane == 0) { ws[wid] = s; ws2[wid] = s2; }
    __syncthreads();
    float mu  = (ws[0] + ws[1] + ws[2] + ws[3]) * (1.f / Hv);
    float var = (ws2[0] + ws2[1] + ws2[2] + ws2[3]) * (1.f / Hv) - mu * mu;
    out[(size_t)row * Hv + t] = (v - mu) * rsqrtf(var + 1e-5f) * g[t] + be[t];
}

// ============================================================================
// Batched NT GEMM, pipelined fragments: C[b,i,j] = scale * A[b,i,:].Kb[b,j,:]
// ============================================================================
__global__ __launch_bounds__(256)
void bgemm_nt128(const float* __restrict__ A, const float* __restrict__ Kb,
                 float* __restrict__ C, float scale)
{
    __shared__ __align__(16) float As[2][16][128];
    __shared__ __align__(16) float Bs[2][16][128];
    const int tid = threadIdx.x;
    const int tx = tid & 15, ty = tid >> 4;
    const int b = blockIdx.z;
    const int i0 = blockIdx.y * 128, j0 = blockIdx.x * 128;

    const float* Ab = A  + ((size_t)b * Nv + i0) * Hv;
    const float* Kp = Kb + ((size_t)b * Nv + j0) * Hv;

    float4 ra[2], rb[2];
    #pragma unroll
    for (int i = 0; i < 2; i++) {
        int lin = tid + i * 256;
        int r = lin >> 2, c4 = (lin & 3) << 2;
        ra[i] = *(const float4*)(Ab + (size_t)r * Hv + c4);
        rb[i] = *(const float4*)(Kp + (size_t)r * Hv + c4);
    }
    #pragma unroll
    for (int i = 0; i < 2; i++) {
        int lin = tid + i * 256;
        int r = lin >> 2, c4 = (lin & 3) << 2;
        As[0][c4+0][r] = ra[i].x; As[0][c4+1][r] = ra[i].y;
        As[0][c4+2][r] = ra[i].z; As[0][c4+3][r] = ra[i].w;
        Bs[0][c4+0][r] = rb[i].x; Bs[0][c4+1][r] = rb[i].y;
        Bs[0][c4+2][r] = rb[i].z; Bs[0][c4+3][r] = rb[i].w;
    }
    __syncthreads();

    unsigned long long acc[4][8];
    #pragma unroll
    for (int i = 0; i < 4; i++)
        #pragma unroll
        for (int j = 0; j < 8; j++) acc[i][j] = 0ull;

    int buf = 0;
    for (int k0 = 0; k0 < Hv; k0 += 16) {
        const bool has_next = (k0 + 16) < Hv;
        if (has_next) {
            #pragma unroll
            for (int i = 0; i < 2; i++) {
                int lin = tid + i * 256;
                int r = lin >> 2, c4 = (lin & 3) << 2;
                ra[i] = *(const float4*)(Ab + (size_t)r * Hv + k0 + 16 + c4);
                rb[i] = *(const float4*)(Kp + (size_t)r * Hv + k0 + 16 + c4);
            }
        }
        unsigned long long faC[4], faN[4];
        float4 fb0C, fb1C, fb0N, fb1N;
        {
            ulonglong2 t0 = *(const ulonglong2*)&As[buf][0][ty * 8];
            ulonglong2 t1 = *(const ulonglong2*)&As[buf][0][ty * 8 + 4];
            faC[0] = t0.x; faC[1] = t0.y; faC[2] = t1.x; faC[3] = t1.y;
        }
        fb0C = *(const float4*)&Bs[buf][0][tx * 8];
        fb1C = *(const float4*)&Bs[buf][0][tx * 8 + 4];
        #pragma unroll
        for (int kk = 0; kk < 16; kk++) {
            if (kk < 15) {
                ulonglong2 t0 = *(const ulonglong2*)&As[buf][kk + 1][ty * 8];
                ulonglong2 t1 = *(const ulonglong2*)&As[buf][kk + 1][ty * 8 + 4];
                faN[0] = t0.x; faN[1] = t0.y; faN[2] = t1.x; faN[3] = t1.y;
                fb0N = *(const float4*)&Bs[buf][kk + 1][tx * 8];
                fb1N = *(const float4*)&Bs[buf][kk + 1][tx * 8 + 4];
            }
            unsigned long long bb[8];
            bb[0] = bcast2(fb0C.x); bb[1] = bcast2(fb0C.y);
            bb[2] = bcast2(fb0C.z); bb[3] = bcast2(fb0C.w);
            bb[4] = bcast2(fb1C.x); bb[5] = bcast2(fb1C.y);
            bb[6] = bcast2(fb1C.z); bb[7] = bcast2(fb1C.w);
            #pragma unroll
            for (int i = 0; i < 4; i++)
                #pragma unroll
                for (int j = 0; j < 8; j++) fma2(acc[i][j], faC[i], bb[j]);
            if (kk < 15) {
                faC[0] = faN[0]; faC[1] = faN[1]; faC[2] = faN[2]; faC[3] = faN[3];
                fb0C = fb0N; fb1C = fb1N;
            }
        }
        if (has_next) {
            int nb = buf ^ 1;
            #pragma unroll
            for (int i = 0; i < 2; i++) {
                int lin = tid + i * 256;
                int r = lin >> 2, c4 = (lin & 3) << 2;
                As[nb][c4+0][r] = ra[i].x; As[nb][c4+1][r] = ra[i].y;
                As[nb][c4+2][r] = ra[i].z; As[nb][c4+3][r] = ra[i].w;
                Bs[nb][c4+0][r] = rb[i].x; Bs[nb][c4+1][r] = rb[i].y;
                Bs[nb][c4+2][r] = rb[i].z; Bs[nb][c4+3][r] = rb[i].w;
            }
            __syncthreads();
            buf = nb;
        }
    }

    #pragma unroll
    for (int ip = 0; ip < 4; ip++) {
        #pragma unroll
        for (int e = 0; e < 2; e++) {
            float* cp = C + ((size_t)b * Nv + i0 + ty * 8 + ip * 2 + e) * Nv + j0 + tx * 8;
            float o[8];
            #pragma unroll
            for (int j = 0; j < 8; j++) {
                float2 p = unpk2(acc[ip][j]);
                o[j] = scale * (e == 0 ? p.x : p.y);
            }
            *(float4*)cp       = *(float4*)&o[0];
            *(float4*)(cp + 4) = *(float4*)&o[4];
        }
    }
}

// -------------------- fused MHA (flash-style, dh=16, N=256) --------------------
__global__ __launch_bounds__(256)
void attn_kernel(const float* __restrict__ qkv, float* __restrict__ out)
{
    int b = blockIdx.x / HEADSv, hd = blockIdx.x % HEADSv;
    __shared__ float Ks[Nv][DHv];
    __shared__ float Vs[Nv][DHv];
    int t = threadIdx.x;
    const float* base = qkv + (size_t)b * Nv * (3 * Hv);
    {
        const float* krow = base + (size_t)t * (3 * Hv) + Hv + hd * DHv;
        const float* vrow = base + (size_t)t * (3 * Hv) + 2 * Hv + hd * DHv;
        #pragma unroll
        for (int c = 0; c < 4; c++) {
            float4 kv4 = *(const float4*)(krow + c * 4);
            Ks[t][c * 4 + 0] = kv4.x; Ks[t][c * 4 + 1] = kv4.y;
            Ks[t][c * 4 + 2] = kv4.z; Ks[t][c * 4 + 3] = kv4.w;
            float4 vv4 = *(const float4*)(vrow + c * 4);
            Vs[t][c * 4 + 0] = vv4.x; Vs[t][c * 4 + 1] = vv4.y;
            Vs[t][c * 4 + 2] = vv4.z; Vs[t][c * 4 + 3] = vv4.w;
        }
    }
    __syncthreads();

    float q[DHv];
    {
        const float* qrow = base + (size_t)t * (3 * Hv) + hd * DHv;
        #pragma unroll
        for (int d = 0; d < DHv; d++) q[d] = qrow[d];
    }
    float m = -INFINITY, sum = 0.f, acc[DHv];
    #pragma unroll
    for (int d = 0; d < DHv; d++) acc[d] = 0.f;

    for (int j = 0; j < Nv; j++) {
        float s = 0.f;
        #pragma unroll
        for (int d = 0; d < DHv; d++) s += q[d] * Ks[j][d];
        s *= 0.25f;
        float mnew = fmaxf(m, s);
        float corr = expf(m - mnew);
        float p = expf(s - mnew);
        sum = sum * corr + p;
        #pragma unroll
        for (int d = 0; d < DHv; d++) acc[d] = acc[d] * corr + p * Vs[j][d];
        m = mnew;
    }
    float inv = 1.f / sum;
    float* orow = out + ((size_t)b * Nv + t) * Hv + hd * DHv;
    #pragma unroll
    for (int d = 0; d < DHv; d++) orow[d] = acc[d] * inv;
}

// -------------------- graph mean over N --------------------
__global__ __launch_bounds__(128)
void graph_mean(const float* __restrict__ node, float* __restrict__ graph)
{
    int b = blockIdx.x, h = threadIdx.x;
    float s = 0.f;
    for (int n = 0; n < Nv; n++) s += node[((size_t)b * Nv + n) * Hv + h];
    graph[b * Hv + h] = s * (1.f / Nv);
}

// -------------------- bq2 = bquery @ Wq --------------------
__global__ __launch_bounds__(128)
void vecmat(const float* __restrict__ v, const float* __restrict__ W, float* __restrict__ out)
{
    int j = threadIdx.x;
    float s = 0.f;
    for (int i = 0; i < Hv; i++) s += v[i] * W[i * Hv + j];
    out[j] = s;
}

// -------------------- baseQ += gq[b] --------------------
__global__ void add_gq(float* __restrict__ baseQ, const float* __restrict__ gq)
{
    int idx = blockIdx.x * blockDim.x + threadIdx.x;
    if (idx < Bv * Nv * Hv) {
        int b = idx / (Nv * Hv);
        int h = idx & (Hv - 1);
        baseQ[idx] += gq[b * Hv + h];
    }
}

// -------------------- greedy decode: single-pass online softmax ---------------
__global__ __launch_bounds__(128)
void decode_kernel(const float* __restrict__ baseLT, const float* __restrict__ cross,
                   float* __restrict__ out_tours, float* __restrict__ out_logp)
{
    int idx = blockIdx.x * blockDim.x + threadIdx.x;
    if (idx >= Bv * Nv) return;
    int b = idx >> 8, s = idx & 255;
    unsigned mask[8] = {0, 0, 0, 0, 0, 0, 0, 0};
    mask[s >> 5] |= 1u << (s & 31);
    const float* blT = baseLT + (size_t)b * Nv * Nv;
    int cur = s;
    float logp = 0.f;
    out_tours[(size_t)idx * TOURLEN] = (float)s;
    for (int step = 1; step < TOURLEN; step++) {
        const float* cr = cross + ((size_t)b * Nv + cur) * Nv;
        float mx = -3.4e38f, sum = 0.f;
        int arg = 0;
        for (int n = 0; n < Nv; n++) {
            bool vis = (mask[n >> 5] >> (n & 31)) & 1u;
            if (vis) continue;
            float v = __ldg(blT + (size_t)n * Nv + s) + __ldg(cr + n);
            if (v > mx) {
                sum = sum * expf(mx - v) + 1.f;
                mx = v;
                arg = n;
            } else {
                sum += expf(v - mx);
            }
        }
        logp -= logf(sum);
        mask[arg >> 5] |= 1u << (arg & 31);
        cur = arg;
        out_tours[(size_t)idx * TOURLEN + step] = (float)arg;
    }
    out_logp[idx] = logp;
}

// -------------------- host orchestration --------------------
extern "C" void kernel_launch(void* const* d_in, const int* in_sizes, int n_in,
                              void* d_out, int out_size)
{
    const float* x      = (const float*)d_in[0];
    const float* init_W = (const float*)d_in[1];
    const float* init_b = (const float*)d_in[2];
    const float* Wqkv   = (const float*)d_in[3];
    const float* bqkv   = (const float*)d_in[4];
    const float* Wo     = (const float*)d_in[5];
    const float* bo     = (const float*)d_in[6];
    const float* W1     = (const float*)d_in[7];
    const float* b1     = (const float*)d_in[8];
    const float* W2     = (const float*)d_in[9];
    const float* b2     = (const float*)d_in[10];
    const float* ln1_g  = (const float*)d_in[11];
    const float* ln1_b  = (const float*)d_in[12];
    const float* ln2_g  = (const float*)d_in[13];
    const float* ln2_b  = (const float*)d_in[14];
    const float* Wquery = (const float*)d_in[15];
    const float* bquery = (const float*)d_in[16];
    const float* Wq     = (const float*)d_in[17];
    const float* Wk     = (const float*)d_in[18];

    float *h, *qkv, *att, *ff, *part, *kbuf, *Mbuf, *baseQ, *graph, *gq;
    float *W1q, *W2q, *W3q, *bq2, *baseLT, *cross;
    cudaGetSymbolAddress((void**)&h,     g_h);
    cudaGetSymbolAddress((void**)&qkv,   g_qkv);
    cudaGetSymbolAddress((void**)&att,   g_att);
    cudaGetSymbolAddress((void**)&ff,    g_ff);
    cudaGetSymbolAddress((void**)&part,  g_part);
    cudaGetSymbolAddress((void**)&kbuf,  g_k);
    cudaGetSymbolAddress((void**)&Mbuf,  g_M);
    cudaGetSymbolAddress((void**)&baseQ, g_baseQ);
    cudaGetSymbolAddress((void**)&graph, g_graph);
    cudaGetSymbolAddress((void**)&gq,    g_gq);
    cudaGetSymbolAddress((void**)&W1q,   g_W1q);
    cudaGetSymbolAddress((void**)&W2q,   g_W2q);
    cudaGetSymbolAddress((void**)&W3q,   g_W3q);
    cudaGetSymbolAddress((void**)&bq2,   g_bq2);
    cudaGetSymbolAddress((void**)&baseLT, g_baseLT);
    cudaGetSymbolAddress((void**)&cross, g_cross);

    const int Mtok = Bv * Nv;    // 16384
    const int MB = Mtok / 128;   // 128 row-blocks

    // ---- init embedding: h = x @ init_W + init_b  (K=16)
    sgemm_k<128, 0><<<dim3(1, MB), 256>>>(
        x, init_W, init_b, nullptr, nullptr, nullptr, h, Mtok, Hv, Din, 0);

    // ---- encoder layers
    for (int l = 0; l < Lv; l++) {
        sgemm_k<128, 0><<<dim3(3, MB), 256>>>(
            h, Wqkv + (size_t)l * Hv * 3 * Hv, bqkv + (size_t)l * 3 * Hv,
            nullptr, nullptr, nullptr, qkv, Mtok, 3 * Hv, Hv, 0);
        attn_kernel<<<Bv * HEADSv, 256>>>(qkv, att);
        // h = LN(h + att @ Wo + bo)
        sgemm_k<128, 2><<<dim3(1, MB), 256>>>(
            att, Wo + (size_t)l * Hv * Hv, bo + (size_t)l * Hv,
            h, ln1_g + (size_t)l * Hv, ln1_b + (size_t)l * Hv, h, Mtok, Hv, Hv, 0);
        sgemm_k<128, 1><<<dim3(DFFv / 128, MB), 256>>>(
            h, W1 + (size_t)l * Hv * DFFv, b1 + (size_t)l * DFFv,
            nullptr, nullptr, nullptr, ff, Mtok, DFFv, Hv, 0);
        // W2 whale: split-K=4 in ONE launch
        sgemm_k<128, 0><<<dim3(1, MB, SPLITK), 256>>>(
            ff, W2 + (size_t)l * DFFv * Hv, nullptr, nullptr, nullptr, nullptr,
            part, Mtok, Hv, DFFv, (size_t)Mtok * Hv);
        reduce_ln<<<Mtok, 128>>>(part, b2 + (size_t)l * Hv, h,
                                 ln2_g + (size_t)l * Hv, ln2_b + (size_t)l * Hv, h);
    }

    // ---- decoder precompute (fp32 path)
    graph_mean<<<Bv, 128>>>(h, graph);
    sgemm_k<128, 0><<<dim3(1, MB), 256>>>(
        h, Wk, nullptr, nullptr, nullptr, nullptr, kbuf, Mtok, Hv, Hv, 0);

    sgemm_k<64, 0><<<dim3(1, 2), 256>>>(Wquery,               Wq, nullptr, nullptr, nullptr, nullptr, W1q, Hv, Hv, Hv, 0);
    sgemm_k<64, 0><<<dim3(1, 2), 256>>>(Wquery + Hv * Hv,     Wq, nullptr, nullptr, nullptr, nullptr, W2q, Hv, Hv, Hv, 0);
    sgemm_k<64, 0><<<dim3(1, 2), 256>>>(Wquery + 2 * Hv * Hv, Wq, nullptr, nullptr, nullptr, nullptr, W3q, Hv, Hv, Hv, 0);
    vecmat<<<1, 128>>>(bquery, Wq, bq2);

    sgemm_k<64, 0><<<dim3(1, 1), 256>>>(graph, W1q, bq2, nullptr, nullptr, nullptr, gq, Bv, Hv, Hv, 0);
    sgemm_k<128, 0><<<dim3(1, MB), 256>>>(
        h, W2q, nullptr, nullptr, nullptr, nullptr, baseQ, Mtok, Hv, Hv, 0);
    add_gq<<<(Bv * Nv * Hv + 255) / 256, 256>>>(baseQ, gq);
    sgemm_k<128, 0><<<dim3(1, MB), 256>>>(
        h, W3q, nullptr, nullptr, nullptr, nullptr, Mbuf, Mtok, Hv, Hv, 0);

    // baseLT[b,n,s] = scale * k_n . q_s  (swapped operands; bit-identical values)
    bgemm_nt128<<<dim3(2, 2, Bv), 256>>>(kbuf, baseQ, baseLT, LSCALE);
    bgemm_nt128<<<dim3(2, 2, Bv), 256>>>(Mbuf, kbuf, cross, LSCALE);

    // ---- greedy decode (coalesced baseLT, single-pass online softmax)
    float* out = (float*)d_out;
    decode_kernel<<<(Bv * Nv + 127) / 128, 128>>>(baseLT, cross, out, out + (size_t)Bv * Nv * TOURLEN);
}

// round 17
// speedup vs baseline: 1.0733x; 1.0733x over previous
#include <cuda_runtime.h>
#include <cuda_bf16.h>
#include <math.h>

#define Bv   64
#define Nv   256
#define Din  16
#define Hv   128
#define Lv   6
#define DFFv 2048
#define HEADSv 8
#define DHv  16
#define TOURLEN 16
#define LSCALE 0.08838834764831845f   /* H^-0.5 */
#define SPLITK 4

// -------------------- device scratch (no allocations allowed) --------------------
__device__ float g_h[Bv*Nv*Hv];
__device__ float g_qkv[Bv*Nv*3*Hv];
__device__ float g_att[Bv*Nv*Hv];
__device__ float g_ff[Bv*Nv*DFFv];
__device__ float g_part[SPLITK*Bv*Nv*Hv];
__device__ float g_k[Bv*Nv*Hv];
__device__ float g_M[Bv*Nv*Hv];
__device__ float g_baseQ[Bv*Nv*Hv];
__device__ float g_graph[Bv*Hv];
__device__ float g_gq[Bv*Hv];
__device__ float g_W1q[Hv*Hv];
__device__ float g_W2q[Hv*Hv];
__device__ float g_W3q[Hv*Hv];
__device__ float g_bq2[Hv];
__device__ float g_baseLT[Bv*Nv*Nv];   // TRANSPOSED: [b][n][s]
__device__ float g_cross[Bv*Nv*Nv];    // [b][c][n]

// -------------------- packed fp32x2 helpers (Blackwell) --------------------
__device__ __forceinline__ unsigned long long bcast2(float x) {
    unsigned long long r;
    asm("mov.b64 %0, {%1, %1};" : "=l"(r) : "f"(x));
    return r;
}
__device__ __forceinline__ void fma2(unsigned long long& d,
                                     unsigned long long a, unsigned long long b) {
    asm("fma.rn.f32x2 %0, %1, %2, %0;" : "+l"(d) : "l"(a), "l"(b));
}
__device__ __forceinline__ float2 unpk2(unsigned long long v) {
    float lo, hi;
    asm("mov.b64 {%0, %1}, %2;" : "=f"(lo), "=f"(hi) : "l"(v));
    return make_float2(lo, hi);
}

// ============================================================================
// SGEMM (R15-proven), BN=128, BK=16, 256 threads, double-buffered, f32x2.
// blockIdx.z = K-slice index: kbeg = z*K/gridDim.z, C += z*strCz.
// EPI: 0 = optional bias, 1 = bias+relu, 2 = bias+residual+LayerNorm (N==128),
//      3 = add per-batch row vector res[(row>>8)*128+col]  (N==128)
// ============================================================================
template<int BM, int EPI>
__global__ __launch_bounds__(256, 2)
void sgemm_k(const float* __restrict__ A, const float* __restrict__ B,
             const float* __restrict__ bias, const float* __restrict__ res,
             const float* __restrict__ lng, const float* __restrict__ lnb,
             float* __restrict__ C, int M, int N, int K, size_t strCz)
{
    constexpr int TM = BM / 16;
    constexpr int TP = TM / 2;
    constexpr int NA = (BM * 16) / 1024;
    __shared__ __align__(16) float As[2][16][BM];
    __shared__ __align__(16) float Bs[2][16][128];

    const int tid = threadIdx.x;
    const int tx = tid & 15, ty = tid >> 4;
    const int bm = blockIdx.y * BM;
    const int bn = blockIdx.x * 128;
    const int kslice = K / gridDim.z;
    const int kbeg = blockIdx.z * kslice;
    const int kend = kbeg + kslice;
    C += (size_t)blockIdx.z * strCz;

    const float* Ab = A + (size_t)bm * K;
    const float* Bb = B + bn;

    float4 ra[NA], rb[2];

    #pragma unroll
    for (int i = 0; i < NA; i++) {
        int lin = tid + i * 256;
        int r = lin >> 2, c4 = (lin & 3) << 2;
        ra[i] = *(const float4*)(Ab + (size_t)r * K + kbeg + c4);
    }
    #pragma unroll
    for (int i = 0; i < 2; i++) {
        int lin = tid + i * 256;
        int r = lin >> 5, c4 = (lin & 31) << 2;
        rb[i] = *(const float4*)(Bb + (size_t)(kbeg + r) * N + c4);
    }
    #pragma unroll
    for (int i = 0; i < NA; i++) {
        int lin = tid + i * 256;
        int r = lin >> 2, c4 = (lin & 3) << 2;
        As[0][c4 + 0][r] = ra[i].x; As[0][c4 + 1][r] = ra[i].y;
        As[0][c4 + 2][r] = ra[i].z; As[0][c4 + 3][r] = ra[i].w;
    }
    #pragma unroll
    for (int i = 0; i < 2; i++) {
        int lin = tid + i * 256;
        int r = lin >> 5, c4 = (lin & 31) << 2;
        *(float4*)&Bs[0][r][c4] = rb[i];
    }
    __syncthreads();

    unsigned long long acc[TP][8];
    #pragma unroll
    for (int i = 0; i < TP; i++)
        #pragma unroll
        for (int j = 0; j < 8; j++) acc[i][j] = 0ull;

    int buf = 0;
    for (int k0 = kbeg; k0 < kend; k0 += 16) {
        const bool has_next = (k0 + 16) < kend;
        if (has_next) {
            #pragma unroll
            for (int i = 0; i < NA; i++) {
                int lin = tid + i * 256;
                int r = lin >> 2, c4 = (lin & 3) << 2;
                ra[i] = *(const float4*)(Ab + (size_t)r * K + k0 + 16 + c4);
            }
            #pragma unroll
            for (int i = 0; i < 2; i++) {
                int lin = tid + i * 256;
                int r = lin >> 5, c4 = (lin & 31) << 2;
                rb[i] = *(const float4*)(Bb + (size_t)(k0 + 16 + r) * N + c4);
            }
        }
        #pragma unroll
        for (int kk = 0; kk < 16; kk++) {
            unsigned long long a2[TP];
            #pragma unroll
            for (int i = 0; i < TP; i += 2) {
                ulonglong2 t = *(const ulonglong2*)&As[buf][kk][ty * TM + i * 2];
                a2[i] = t.x; a2[i + 1] = t.y;
            }
            float4 bf0 = *(const float4*)&Bs[buf][kk][tx * 8];
            float4 bf1 = *(const float4*)&Bs[buf][kk][tx * 8 + 4];
            unsigned long long bb[8];
            bb[0] = bcast2(bf0.x); bb[1] = bcast2(bf0.y);
            bb[2] = bcast2(bf0.z); bb[3] = bcast2(bf0.w);
            bb[4] = bcast2(bf1.x); bb[5] = bcast2(bf1.y);
            bb[6] = bcast2(bf1.z); bb[7] = bcast2(bf1.w);
            #pragma unroll
            for (int i = 0; i < TP; i++)
                #pragma unroll
                for (int j = 0; j < 8; j++) fma2(acc[i][j], a2[i], bb[j]);
        }
        if (has_next) {
            int nb = buf ^ 1;
            #pragma unroll
            for (int i = 0; i < NA; i++) {
                int lin = tid + i * 256;
                int r = lin >> 2, c4 = (lin & 3) << 2;
                As[nb][c4 + 0][r] = ra[i].x; As[nb][c4 + 1][r] = ra[i].y;
                As[nb][c4 + 2][r] = ra[i].z; As[nb][c4 + 3][r] = ra[i].w;
            }
            #pragma unroll
            for (int i = 0; i < 2; i++) {
                int lin = tid + i * 256;
                int r = lin >> 5, c4 = (lin & 31) << 2;
                *(float4*)&Bs[nb][r][c4] = rb[i];
            }
            __syncthreads();
            buf = nb;
        }
    }

    // ---- epilogue
    float bv[8] = {0.f,0.f,0.f,0.f,0.f,0.f,0.f,0.f};
    if (bias) {
        *(float4*)&bv[0] = *(const float4*)(bias + bn + tx * 8);
        *(float4*)&bv[4] = *(const float4*)(bias + bn + tx * 8 + 4);
    }

    if (EPI == 2) {
        float gv[8], be[8];
        *(float4*)&gv[0] = *(const float4*)(lng + tx * 8);
        *(float4*)&gv[4] = *(const float4*)(lng + tx * 8 + 4);
        *(float4*)&be[0] = *(const float4*)(lnb + tx * 8);
        *(float4*)&be[4] = *(const float4*)(lnb + tx * 8 + 4);
        #pragma unroll
        for (int ip = 0; ip < TP; ip++) {
            #pragma unroll
            for (int e = 0; e < 2; e++) {
                int row = bm + ty * TM + ip * 2 + e;
                const float* rp = res + (size_t)row * 128 + tx * 8;
                float4 r0 = *(const float4*)rp;
                float4 r1 = *(const float4*)(rp + 4);
                float v[8];
                #pragma unroll
                for (int j = 0; j < 8; j++) {
                    float2 p = unpk2(acc[ip][j]);
                    v[j] = (e == 0 ? p.x : p.y) + bv[j];
                }
                v[0] += r0.x; v[1] += r0.y; v[2] += r0.z; v[3] += r0.w;
                v[4] += r1.x; v[5] += r1.y; v[6] += r1.z; v[7] += r1.w;
                float s = 0.f, s2 = 0.f;
                #pragma unroll
                for (int j = 0; j < 8; j++) { s += v[j]; s2 += v[j] * v[j]; }
                #pragma unroll
                for (int m = 8; m >= 1; m >>= 1) {
                    s  += __shfl_xor_sync(0xffffffffu, s,  m);
                    s2 += __shfl_xor_sync(0xffffffffu, s2, m);
                }
                float mu  = s * (1.f / 128.f);
                float var = s2 * (1.f / 128.f) - mu * mu;
                float rs  = rsqrtf(var + 1e-5f);
                float o[8];
                #pragma unroll
                for (int j = 0; j < 8; j++) o[j] = (v[j] - mu) * rs * gv[j] + be[j];
                float* cp = C + (size_t)row * 128 + tx * 8;
                *(float4*)cp       = *(float4*)&o[0];
                *(float4*)(cp + 4) = *(float4*)&o[4];
            }
        }
    } else {
        #pragma unroll
        for (int ip = 0; ip < TP; ip++) {
            #pragma unroll
            for (int e = 0; e < 2; e++) {
                int row = bm + ty * TM + ip * 2 + e;
                float gq0[8] = {0.f,0.f,0.f,0.f,0.f,0.f,0.f,0.f};
                if (EPI == 3) {
                    const float* gp = res + (size_t)(row >> 8) * 128 + tx * 8;
                    *(float4*)&gq0[0] = *(const float4*)gp;
                    *(float4*)&gq0[4] = *(const float4*)(gp + 4);
                }
                float o[8];
                #pragma unroll
                for (int j = 0; j < 8; j++) {
                    float2 p = unpk2(acc[ip][j]);
                    float v = (e == 0 ? p.x : p.y) + bv[j] + gq0[j];
                    if (EPI == 1) v = fmaxf(v, 0.f);
                    o[j] = v;
                }
                float* cp = C + (size_t)row * N + bn + tx * 8;
                *(float4*)cp       = *(float4*)&o[0];
                *(float4*)(cp + 4) = *(float4*)&o[4];
            }
        }
    }
}

// ---- split-K reduce + bias + residual + LayerNorm (R13-proven)
__global__ __launch_bounds__(128)
void reduce_ln(const float* __restrict__ part, const float* __restrict__ bias,
               const float* __restrict__ res, const float* __restrict__ g,
               const float* __restrict__ be, float* __restrict__ out)
{
    const int row = blockIdx.x, t = threadIdx.x;
    const size_t stride = (size_t)Bv * Nv * Hv;
    float v = part[(size_t)row * Hv + t];
    #pragma unroll
    for (int z = 1; z < SPLITK; z++) v += part[z * stride + (size_t)row * Hv + t];
    v += bias[t] + res[(size_t)row * Hv + t];

    __shared__ float ws[4], ws2[4];
    int lane = t & 31, wid = t >> 5;
    float s = v, s2 = v * v;
    #pragma unroll
    for (int o = 16; o > 0; o >>= 1) {
        s  += __shfl_xor_sync(0xffffffffu, s,  o);
        s2 += __shfl_xor_sync(0xffffffffu, s2, o);
    }
    if (lane == 0) { ws[wid] = s; ws2[wid] = s2; }
    __syncthreads();
    float mu  = (ws[0] + ws[1] + ws[2] + ws[3]) * (1.f / Hv);
    float var = (ws2[0] + ws2[1] + ws2[2] + ws2[3]) * (1.f / Hv) - mu * mu;
    out[(size_t)row * Hv + t] = (v - mu) * rsqrtf(var + 1e-5f) * g[t] + be[t];
}

// ============================================================================
// Batched NT GEMM (R15-proven): C[b,i,j] = scale * A[b,i,:].Kb[b,j,:] (K=H=128)
// ============================================================================
__global__ __launch_bounds__(256, 2)
void bgemm_nt128(const float* __restrict__ A, const float* __restrict__ Kb,
                 float* __restrict__ C, float scale)
{
    __shared__ __align__(16) float As[2][16][128];
    __shared__ __align__(16) float Bs[2][16][128];
    const int tid = threadIdx.x;
    const int tx = tid & 15, ty = tid >> 4;
    const int b = blockIdx.z;
    const int i0 = blockIdx.y * 128, j0 = blockIdx.x * 128;

    const float* Ab = A  + ((size_t)b * Nv + i0) * Hv;
    const float* Kp = Kb + ((size_t)b * Nv + j0) * Hv;

    float4 ra[2], rb[2];
    #pragma unroll
    for (int i = 0; i < 2; i++) {
        int lin = tid + i * 256;
        int r = lin >> 2, c4 = (lin & 3) << 2;
        ra[i] = *(const float4*)(Ab + (size_t)r * Hv + c4);
        rb[i] = *(const float4*)(Kp + (size_t)r * Hv + c4);
    }
    #pragma unroll
    for (int i = 0; i < 2; i++) {
        int lin = tid + i * 256;
        int r = lin >> 2, c4 = (lin & 3) << 2;
        As[0][c4+0][r] = ra[i].x; As[0][c4+1][r] = ra[i].y;
        As[0][c4+2][r] = ra[i].z; As[0][c4+3][r] = ra[i].w;
        Bs[0][c4+0][r] = rb[i].x; Bs[0][c4+1][r] = rb[i].y;
        Bs[0][c4+2][r] = rb[i].z; Bs[0][c4+3][r] = rb[i].w;
    }
    __syncthreads();

    unsigned long long acc[4][8];
    #pragma unroll
    for (int i = 0; i < 4; i++)
        #pragma unroll
        for (int j = 0; j < 8; j++) acc[i][j] = 0ull;

    int buf = 0;
    for (int k0 = 0; k0 < Hv; k0 += 16) {
        const bool has_next = (k0 + 16) < Hv;
        if (has_next) {
            #pragma unroll
            for (int i = 0; i < 2; i++) {
                int lin = tid + i * 256;
                int r = lin >> 2, c4 = (lin & 3) << 2;
                ra[i] = *(const float4*)(Ab + (size_t)r * Hv + k0 + 16 + c4);
                rb[i] = *(const float4*)(Kp + (size_t)r * Hv + k0 + 16 + c4);
            }
        }
        #pragma unroll
        for (int kk = 0; kk < 16; kk++) {
            unsigned long long a2[4];
            {
                ulonglong2 t0 = *(const ulonglong2*)&As[buf][kk][ty * 8];
                ulonglong2 t1 = *(const ulonglong2*)&As[buf][kk][ty * 8 + 4];
                a2[0] = t0.x; a2[1] = t0.y; a2[2] = t1.x; a2[3] = t1.y;
            }
            float4 bf0 = *(const float4*)&Bs[buf][kk][tx * 8];
            float4 bf1 = *(const float4*)&Bs[buf][kk][tx * 8 + 4];
            unsigned long long bb[8];
            bb[0] = bcast2(bf0.x); bb[1] = bcast2(bf0.y);
            bb[2] = bcast2(bf0.z); bb[3] = bcast2(bf0.w);
            bb[4] = bcast2(bf1.x); bb[5] = bcast2(bf1.y);
            bb[6] = bcast2(bf1.z); bb[7] = bcast2(bf1.w);
            #pragma unroll
            for (int i = 0; i < 4; i++)
                #pragma unroll
                for (int j = 0; j < 8; j++) fma2(acc[i][j], a2[i], bb[j]);
        }
        if (has_next) {
            int nb = buf ^ 1;
            #pragma unroll
            for (int i = 0; i < 2; i++) {
                int lin = tid + i * 256;
                int r = lin >> 2, c4 = (lin & 3) << 2;
                As[nb][c4+0][r] = ra[i].x; As[nb][c4+1][r] = ra[i].y;
                As[nb][c4+2][r] = ra[i].z; As[nb][c4+3][r] = ra[i].w;
                Bs[nb][c4+0][r] = rb[i].x; Bs[nb][c4+1][r] = rb[i].y;
                Bs[nb][c4+2][r] = rb[i].z; Bs[nb][c4+3][r] = rb[i].w;
            }
            __syncthreads();
            buf = nb;
        }
    }

    #pragma unroll
    for (int ip = 0; ip < 4; ip++) {
        #pragma unroll
        for (int e = 0; e < 2; e++) {
            float* cp = C + ((size_t)b * Nv + i0 + ty * 8 + ip * 2 + e) * Nv + j0 + tx * 8;
            float o[8];
            #pragma unroll
            for (int j = 0; j < 8; j++) {
                float2 p = unpk2(acc[ip][j]);
                o[j] = scale * (e == 0 ? p.x : p.y);
            }
            *(float4*)cp       = *(float4*)&o[0];
            *(float4*)(cp + 4) = *(float4*)&o[4];
        }
    }
}

// -------------------- fused MHA (flash-style, dh=16, N=256) --------------------
__global__ __launch_bounds__(256)
void attn_kernel(const float* __restrict__ qkv, float* __restrict__ out)
{
    int b = blockIdx.x / HEADSv, hd = blockIdx.x % HEADSv;
    __shared__ float Ks[Nv][DHv];
    __shared__ float Vs[Nv][DHv];
    int t = threadIdx.x;
    const float* base = qkv + (size_t)b * Nv * (3 * Hv);
    {
        const float* krow = base + (size_t)t * (3 * Hv) + Hv + hd * DHv;
        const float* vrow = base + (size_t)t * (3 * Hv) + 2 * Hv + hd * DHv;
        #pragma unroll
        for (int c = 0; c < 4; c++) {
            float4 kv4 = *(const float4*)(krow + c * 4);
            Ks[t][c * 4 + 0] = kv4.x; Ks[t][c * 4 + 1] = kv4.y;
            Ks[t][c * 4 + 2] = kv4.z; Ks[t][c * 4 + 3] = kv4.w;
            float4 vv4 = *(const float4*)(vrow + c * 4);
            Vs[t][c * 4 + 0] = vv4.x; Vs[t][c * 4 + 1] = vv4.y;
            Vs[t][c * 4 + 2] = vv4.z; Vs[t][c * 4 + 3] = vv4.w;
        }
    }
    __syncthreads();

    float q[DHv];
    {
        const float* qrow = base + (size_t)t * (3 * Hv) + hd * DHv;
        #pragma unroll
        for (int d = 0; d < DHv; d++) q[d] = qrow[d];
    }
    float m = -INFINITY, sum = 0.f, acc[DHv];
    #pragma unroll
    for (int d = 0; d < DHv; d++) acc[d] = 0.f;

    for (int j = 0; j < Nv; j++) {
        float s = 0.f;
        #pragma unroll
        for (int d = 0; d < DHv; d++) s += q[d] * Ks[j][d];
        s *= 0.25f;
        float mnew = fmaxf(m, s);
        float corr = expf(m - mnew);
        float p = expf(s - mnew);
        sum = sum * corr + p;
        #pragma unroll
        for (int d = 0; d < DHv; d++) acc[d] = acc[d] * corr + p * Vs[j][d];
        m = mnew;
    }
    float inv = 1.f / sum;
    float* orow = out + ((size_t)b * Nv + t) * Hv + hd * DHv;
    #pragma unroll
    for (int d = 0; d < DHv; d++) orow[d] = acc[d] * inv;
}

// -------------------- graph mean over N --------------------
__global__ __launch_bounds__(128)
void graph_mean(const float* __restrict__ node, float* __restrict__ graph)
{
    int b = blockIdx.x, h = threadIdx.x;
    float s = 0.f;
    for (int n = 0; n < Nv; n++) s += node[((size_t)b * Nv + n) * Hv + h];
    graph[b * Hv + h] = s * (1.f / Nv);
}

// -------------------- bq2 = bquery @ Wq --------------------
__global__ __launch_bounds__(128)
void vecmat(const float* __restrict__ v, const float* __restrict__ W, float* __restrict__ out)
{
    int j = threadIdx.x;
    float s = 0.f;
    for (int i = 0; i < Hv; i++) s += v[i] * W[i * Hv + j];
    out[j] = s;
}

// -------------------- greedy decode: single-pass online softmax ---------------
__global__ __launch_bounds__(128)
void decode_kernel(const float* __restrict__ baseLT, const float* __restrict__ cross,
                   float* __restrict__ out_tours, float* __restrict__ out_logp)
{
    int idx = blockIdx.x * blockDim.x + threadIdx.x;
    if (idx >= Bv * Nv) return;
    int b = idx >> 8, s = idx & 255;
    unsigned mask[8] = {0, 0, 0, 0, 0, 0, 0, 0};
    mask[s >> 5] |= 1u << (s & 31);
    const float* blT = baseLT + (size_t)b * Nv * Nv;
    int cur = s;
    float logp = 0.f;
    out_tours[(size_t)idx * TOURLEN] = (float)s;
    for (int step = 1; step < TOURLEN; step++) {
        const float* cr = cross + ((size_t)b * Nv + cur) * Nv;
        float mx = -3.4e38f, sum = 0.f;
        int arg = 0;
        for (int n = 0; n < Nv; n++) {
            bool vis = (mask[n >> 5] >> (n & 31)) & 1u;
            if (vis) continue;
            float v = __ldg(blT + (size_t)n * Nv + s) + __ldg(cr + n);
            if (v > mx) {
                sum = sum * expf(mx - v) + 1.f;
                mx = v;
                arg = n;
            } else {
                sum += expf(v - mx);
            }
        }
        logp -= logf(sum);
        mask[arg >> 5] |= 1u << (arg & 31);
        cur = arg;
        out_tours[(size_t)idx * TOURLEN + step] = (float)arg;
    }
    out_logp[idx] = logp;
}

// -------------------- host orchestration --------------------
extern "C" void kernel_launch(void* const* d_in, const int* in_sizes, int n_in,
                              void* d_out, int out_size)
{
    const float* x      = (const float*)d_in[0];
    const float* init_W = (const float*)d_in[1];
    const float* init_b = (const float*)d_in[2];
    const float* Wqkv   = (const float*)d_in[3];
    const float* bqkv   = (const float*)d_in[4];
    const float* Wo     = (const float*)d_in[5];
    const float* bo     = (const float*)d_in[6];
    const float* W1     = (const float*)d_in[7];
    const float* b1     = (const float*)d_in[8];
    const float* W2     = (const float*)d_in[9];
    const float* b2     = (const float*)d_in[10];
    const float* ln1_g  = (const float*)d_in[11];
    const float* ln1_b  = (const float*)d_in[12];
    const float* ln2_g  = (const float*)d_in[13];
    const float* ln2_b  = (const float*)d_in[14];
    const float* Wquery = (const float*)d_in[15];
    const float* bquery = (const float*)d_in[16];
    const float* Wq     = (const float*)d_in[17];
    const float* Wk     = (const float*)d_in[18];

    float *h, *qkv, *att, *ff, *part, *kbuf, *Mbuf, *baseQ, *graph, *gq;
    float *W1q, *W2q, *W3q, *bq2, *baseLT, *cross;
    cudaGetSymbolAddress((void**)&h,     g_h);
    cudaGetSymbolAddress((void**)&qkv,   g_qkv);
    cudaGetSymbolAddress((void**)&att,   g_att);
    cudaGetSymbolAddress((void**)&ff,    g_ff);
    cudaGetSymbolAddress((void**)&part,  g_part);
    cudaGetSymbolAddress((void**)&kbuf,  g_k);
    cudaGetSymbolAddress((void**)&Mbuf,  g_M);
    cudaGetSymbolAddress((void**)&baseQ, g_baseQ);
    cudaGetSymbolAddress((void**)&graph, g_graph);
    cudaGetSymbolAddress((void**)&gq,    g_gq);
    cudaGetSymbolAddress((void**)&W1q,   g_W1q);
    cudaGetSymbolAddress((void**)&W2q,   g_W2q);
    cudaGetSymbolAddress((void**)&W3q,   g_W3q);
    cudaGetSymbolAddress((void**)&bq2,   g_bq2);
    cudaGetSymbolAddress((void**)&baseLT, g_baseLT);
    cudaGetSymbolAddress((void**)&cross, g_cross);

    const int Mtok = Bv * Nv;    // 16384
    const int MB = Mtok / 128;   // 128 row-blocks

    // ---- init embedding: h = x @ init_W + init_b  (K=16)
    sgemm_k<128, 0><<<dim3(1, MB), 256>>>(
        x, init_W, init_b, nullptr, nullptr, nullptr, h, Mtok, Hv, Din, 0);

    // ---- encoder layers
    for (int l = 0; l < Lv; l++) {
        sgemm_k<128, 0><<<dim3(3, MB), 256>>>(
            h, Wqkv + (size_t)l * Hv * 3 * Hv, bqkv + (size_t)l * 3 * Hv,
            nullptr, nullptr, nullptr, qkv, Mtok, 3 * Hv, Hv, 0);
        attn_kernel<<<Bv * HEADSv, 256>>>(qkv, att);
        // h = LN(h + att @ Wo + bo)
        sgemm_k<128, 2><<<dim3(1, MB), 256>>>(
            att, Wo + (size_t)l * Hv * Hv, bo + (size_t)l * Hv,
            h, ln1_g + (size_t)l * Hv, ln1_b + (size_t)l * Hv, h, Mtok, Hv, Hv, 0);
        sgemm_k<128, 1><<<dim3(DFFv / 128, MB), 256>>>(
            h, W1 + (size_t)l * Hv * DFFv, b1 + (size_t)l * DFFv,
            nullptr, nullptr, nullptr, ff, Mtok, DFFv, Hv, 0);
        // W2 whale: split-K=4 in ONE launch (512 CTAs -> 2 CTAs/SM)
        sgemm_k<128, 0><<<dim3(1, MB, SPLITK), 256>>>(
            ff, W2 + (size_t)l * DFFv * Hv, nullptr, nullptr, nullptr, nullptr,
            part, Mtok, Hv, DFFv, (size_t)Mtok * Hv);
        reduce_ln<<<Mtok, 128>>>(part, b2 + (size_t)l * Hv, h,
                                 ln2_g + (size_t)l * Hv, ln2_b + (size_t)l * Hv, h);
    }

    // ---- decoder precompute (fp32 path)
    graph_mean<<<Bv, 128>>>(h, graph);
    sgemm_k<128, 0><<<dim3(1, MB), 256>>>(
        h, Wk, nullptr, nullptr, nullptr, nullptr, kbuf, Mtok, Hv, Hv, 0);

    sgemm_k<64, 0><<<dim3(1, 2), 256>>>(Wquery,               Wq, nullptr, nullptr, nullptr, nullptr, W1q, Hv, Hv, Hv, 0);
    sgemm_k<64, 0><<<dim3(1, 2), 256>>>(Wquery + Hv * Hv,     Wq, nullptr, nullptr, nullptr, nullptr, W2q, Hv, Hv, Hv, 0);
    sgemm_k<64, 0><<<dim3(1, 2), 256>>>(Wquery + 2 * Hv * Hv, Wq, nullptr, nullptr, nullptr, nullptr, W3q, Hv, Hv, Hv, 0);
    vecmat<<<1, 128>>>(bquery, Wq, bq2);

    sgemm_k<64, 0><<<dim3(1, 1), 256>>>(graph, W1q, bq2, nullptr, nullptr, nullptr, gq, Bv, Hv, Hv, 0);
    // baseQ = h @ W2q + gq[b]  (gq add fused in epilogue, EPI=3)
    sgemm_k<128, 3><<<dim3(1, MB), 256>>>(
        h, W2q, nullptr, gq, nullptr, nullptr, baseQ, Mtok, Hv, Hv, 0);
    sgemm_k<128, 0><<<dim3(1, MB), 256>>>(
        h, W3q, nullptr, nullptr, nullptr, nullptr, Mbuf, Mtok, Hv, Hv, 0);

    // baseLT[b,n,s] = scale * k_n . q_s  (swapped operands; bit-identical values)
    bgemm_nt128<<<dim3(2, 2, Bv), 256>>>(kbuf, baseQ, baseLT, LSCALE);
    bgemm_nt128<<<dim3(2, 2, Bv), 256>>>(Mbuf, kbuf, cross, LSCALE);

    // ---- greedy decode (coalesced baseLT, single-pass online softmax)
    float* out = (float*)d_out;
    decode_kernel<<<(Bv * Nv + 127) / 128, 128>>>(baseLT, cross, out, out + (size_t)Bv * Nv * TOURLEN);
}